// round 2
// baseline (speedup 1.0000x reference)
#include <cuda_runtime.h>
#include <cstdint>
#include <cstddef>

// ---------------------------------------------------------------------------
// Problem constants
// ---------------------------------------------------------------------------
#define A_N   2000
#define P_N   20000
#define E_N   200000
#define MUL0  128
#define MUL1  64
#define DIM   320
#define MID0  192
#define WNUM  384

#define INV_SQRT10   0.31622776601683794f
#define INV_SQRT64   0.125f
#define INV_SQRT100  0.1f
#define INV_SQRT128  0.08838834764831845f
#define INV_SQRT192  0.07216878364870323f
#define INV_SQRT3    0.5773502691896258f

typedef unsigned long long ull;

// ---------------------------------------------------------------------------
// Device scratch
// ---------------------------------------------------------------------------
__device__ __align__(16) float g_s0[A_N * MUL0];
__device__ __align__(16) float g_s1[A_N * MID0];
__device__ __align__(16) float g_w[(size_t)E_N * WNUM];   // weights in SORTED edge order
__device__ int g_cnt[P_N];
__device__ int g_cur[P_N];
__device__ int g_off[P_N + 1];
__device__ int g_ord[E_N];

// ---------------------------------------------------------------------------
// PTX helpers
// ---------------------------------------------------------------------------
__device__ __forceinline__ void fma2(ull& d, ull a, ull b, ull c) {
    asm("fma.rn.f32x2 %0, %1, %2, %3;" : "=l"(d) : "l"(a), "l"(b), "l"(c));
}
__device__ __forceinline__ float2 unpack2(ull v) {
    float2 r;
    asm("mov.b64 {%0, %1}, %2;" : "=f"(r.x), "=f"(r.y) : "l"(v));
    return r;
}
__device__ __forceinline__ ull dupf(float v) {
    ull r;
    asm("mov.b64 %0, {%1, %1};" : "=l"(r) : "f"(v));
    return r;
}
__device__ __forceinline__ void cp16(uint32_t s, const void* g) {
    asm volatile("cp.async.cg.shared.global [%0], [%1], 16;" :: "r"(s), "l"(g));
}
#define CP_COMMIT() asm volatile("cp.async.commit_group;")
#define CP_WAIT2()  asm volatile("cp.async.wait_group 2;")

// ---------------------------------------------------------------------------
// K0: zero aux counters
// ---------------------------------------------------------------------------
__global__ void zero_aux_kernel() {
    int i = blockIdx.x * blockDim.x + threadIdx.x;
    if (i < P_N) { g_cnt[i] = 0; g_cur[i] = 0; }
}

// ---------------------------------------------------------------------------
// K1: sender transform (unchanged from round 1)
// ---------------------------------------------------------------------------
__global__ __launch_bounds__(192) void sender_kernel(
    const float* __restrict__ sin_, const float* __restrict__ sattr,
    const float* __restrict__ w0,   const float* __restrict__ w1) {
    __shared__ float xs[DIM];
    int a = blockIdx.x, tid = threadIdx.x;
    float at = sattr[a];
    for (int idx = tid; idx < DIM; idx += 192)
        xs[idx] = sin_[(size_t)a * DIM + idx] * at;
    __syncthreads();
    if (tid < MUL0) {
        float acc = 0.f;
        #pragma unroll 8
        for (int u = 0; u < MUL0; u++) acc += xs[u] * w0[u * MUL0 + tid];
        g_s0[a * MUL0 + tid] = acc * INV_SQRT128;
    }
    {
        int o = tid, v = o / 3, m = o - v * 3;
        float acc = 0.f;
        #pragma unroll 8
        for (int u = 0; u < MUL1; u++) acc += xs[MUL0 + u * 3 + m] * w1[u * MUL1 + v];
        g_s1[a * MID0 + o] = acc * INV_SQRT64;
    }
}

// ---------------------------------------------------------------------------
// K2/K3/K4: CSR sort of edges by destination
// ---------------------------------------------------------------------------
__global__ void hist_kernel(const int* __restrict__ edst) {
    for (int e = blockIdx.x * blockDim.x + threadIdx.x; e < E_N;
         e += gridDim.x * blockDim.x)
        atomicAdd(&g_cnt[edst[e]], 1);
}

__global__ __launch_bounds__(1024) void scan_kernel() {
    __shared__ int part[1024];
    int t = threadIdx.x;
    int base = t * 20;
    int local[20];
    int s = 0;
    #pragma unroll
    for (int i = 0; i < 20; i++) {
        int c = (base + i < P_N) ? g_cnt[base + i] : 0;
        local[i] = s; s += c;
    }
    part[t] = s;
    __syncthreads();
    for (int off = 1; off < 1024; off <<= 1) {
        int v = (t >= off) ? part[t - off] : 0;
        __syncthreads();
        part[t] += v;
        __syncthreads();
    }
    int pre = (t > 0) ? part[t - 1] : 0;
    #pragma unroll
    for (int i = 0; i < 20; i++)
        if (base + i < P_N) g_off[base + i] = pre + local[i];
    if (t == 1023) g_off[P_N] = part[1023];
}

__global__ void scatter_kernel(const int* __restrict__ edst) {
    for (int e = blockIdx.x * blockDim.x + threadIdx.x; e < E_N;
         e += gridDim.x * blockDim.x) {
        int d = edst[e];
        int pos = g_off[d] + atomicAdd(&g_cur[d], 1);
        g_ord[pos] = e;
    }
}

// ---------------------------------------------------------------------------
// K5: weight GEMM.  weight[j] = silu(escal[eid]@fc_w1/sqrt10) @ fc_w2 / sqrt100
//     j = sorted edge index, eid = g_ord[j].  32 edges/block, 384 threads.
// ---------------------------------------------------------------------------
__global__ __launch_bounds__(384) void weight_kernel(
    const float* __restrict__ escal,
    const float* __restrict__ fw1, const float* __restrict__ fw2) {
    __shared__ int    s_eid[32];
    __shared__ float  s_scal[32 * 10];
    __shared__ float2 s_h[32 * 100];

    int tid = threadIdx.x;
    int e0  = blockIdx.x * 32;

    if (tid < 32) s_eid[tid] = g_ord[e0 + tid];
    __syncthreads();
    if (tid < 320) {
        int t = tid / 10, b = tid - t * 10;
        s_scal[tid] = escal[(size_t)s_eid[t] * 10 + b];
    }
    __syncthreads();

    // phase A: hidden activations, with 1/sqrt(100) folded in
    for (int idx = tid; idx < 3200; idx += 384) {
        int t = idx / 100, k = idx - t * 100;
        float acc = 0.f;
        #pragma unroll
        for (int b = 0; b < 10; b++) acc += s_scal[t * 10 + b] * fw1[b * 100 + k];
        acc *= INV_SQRT10;
        float h = acc / (1.f + __expf(-acc)) * INV_SQRT100;
        s_h[t * 100 + k] = make_float2(h, h);
    }
    __syncthreads();

    int tx = tid % 96, ty = tid / 96;
    const ulonglong2* W2 = reinterpret_cast<const ulonglong2*>(fw2);
    const ull* H = reinterpret_cast<const ull*>(s_h);

    ull acc[8][2];
    #pragma unroll
    for (int i = 0; i < 8; i++) { acc[i][0] = 0ull; acc[i][1] = 0ull; }

    #pragma unroll 4
    for (int k = 0; k < 100; k++) {
        ulonglong2 w = W2[k * 96 + tx];
        #pragma unroll
        for (int tt = 0; tt < 8; tt++) {
            ull hv = H[(ty + 4 * tt) * 100 + k];
            fma2(acc[tt][0], hv, w.x, acc[tt][0]);
            fma2(acc[tt][1], hv, w.y, acc[tt][1]);
        }
    }

    #pragma unroll
    for (int tt = 0; tt < 8; tt++) {
        int t = ty + 4 * tt;
        float2 lo = unpack2(acc[tt][0]), hi = unpack2(acc[tt][1]);
        *reinterpret_cast<float4*>(&g_w[(size_t)(e0 + t) * WNUM + 4 * tx]) =
            make_float4(lo.x, lo.y, hi.x, hi.y);
    }
}

// ---------------------------------------------------------------------------
// K6: fused accumulate + receiver kernel.
//   8 receivers/block, 320 threads. Edge data streamed via cp.async pipeline
//   (4 buffers, prefetch distance 2). r accumulated directly into PACKED
//   pair-interleaved smem so the final GEMM runs on float4-LDS + fma.rn.f32x2.
//
// Packed layouts (4 pairs of receivers, i = 2p + half):
//   rp0[p][k]    k<192   scalar r            float2 (i even, i odd)
//   rpv[p][m][c] c<192   vector r component  rows padded to 388 floats
//   xp0[p][d]    d<128   scalar x
//   xpv[p][m][u] u<64    vector x component  rows padded to 132 floats
// ---------------------------------------------------------------------------
#define OFF_RP0 0
#define OFF_RPV 1536
#define RPV_STR 388
#define OFF_XP0 6192
#define OFF_XPV 7216
#define XPV_STR 132
#define OFF_STG 8800
#define STG_STR 708           // w[384] g0[128] g1[192] sh[4]
#define NBUF    4
#define CHUNK   128
#define SMF     (OFF_STG + NBUF * STG_STR)   // 11632 floats = 46528 B

__device__ __forceinline__ void stage_async(uint32_t smb, int buf, int jglob,
                                            int eid, int src,
                                            const float* __restrict__ eattr) {
    uint32_t st = smb + (uint32_t)(OFF_STG + buf * STG_STR) * 4u;
    int t = threadIdx.x;
    if (t < 96)        cp16(st + 16u * t,                 g_w  + (size_t)jglob * WNUM + 4 * t);
    else if (t < 128)  cp16(st + 1536u + 16u * (t - 96),  g_s0 + (size_t)src * MUL0 + 4 * (t - 96));
    else if (t < 176)  cp16(st + 2048u + 16u * (t - 128), g_s1 + (size_t)src * MID0 + 4 * (t - 128));
    else if (t == 176) cp16(st + 2816u,                   eattr + (size_t)eid * 4);
}

__device__ __forceinline__ void edge_accum(float* __restrict__ sm, int buf, int i) {
    const float* st = sm + OFF_STG + buf * STG_STR;
    float sh0 = st[704], sx = st[705], sy = st[706], sz = st[707];
    int half = i & 1, pr = i >> 1;
    for (int c = threadIdx.x; c < 768; c += 320) {
        float val; int addr;
        if (c < 192) {
            if (c < 128) {
                val = st[c] * st[384 + c] * sh0;                     // w0*g0*sh0
            } else {
                int v = c - 128;
                const float* g = st + 512 + 3 * v;
                val = st[320 + v] * (g[0] * sx + g[1] * sy + g[2] * sz) * INV_SQRT3;
            }
            addr = OFF_RP0 + pr * 384 + c * 2 + half;
        } else if (c < 576) {
            int o = c - 192, u = o / 3, m = o - 3 * u;
            val  = st[128 + u] * st[384 + u] * st[705 + m];          // w1*g0*sh1
            addr = OFF_RPV + (pr * 3 + m) * RPV_STR + u * 2 + half;
        } else {
            int o = c - 576, v = o / 3, m = o - 3 * v;
            val  = st[256 + v] * st[512 + o] * sh0;                  // w2*g1*sh0
            addr = OFF_RPV + (pr * 3 + m) * RPV_STR + (128 + v) * 2 + half;
        }
        sm[addr] += val;
    }
}

__global__ __launch_bounds__(320, 3) void fused_recv_kernel(
    const float* __restrict__ rin,  const float* __restrict__ rattr,
    const int*   __restrict__ esrc, const float* __restrict__ eattr,
    const float* __restrict__ scw0, const float* __restrict__ scw1,
    const float* __restrict__ l2w0, const float* __restrict__ l2w1,
    const float* __restrict__ l3w,  float* __restrict__ out) {
    __shared__ __align__(16) float sm[SMF];
    __shared__ int s_eid[CHUNK], s_src[CHUNK], s_ri[CHUNK], s_off[9];
    __shared__ float s_att[8], s_ang[8];

    int tid = threadIdx.x;
    int p0  = blockIdx.x * 8;

    if (tid < 9) s_off[tid] = g_off[p0 + tid];
    if (tid < 8) s_att[tid] = rattr[p0 + tid];
    __syncthreads();

    // load x into packed layout (with attr), zero r accumulators
    for (int idx = tid; idx < 8 * DIM; idx += 320) {
        int i = idx / DIM, d = idx - i * DIM;
        float v = rin[(size_t)(p0 + i) * DIM + d] * s_att[i];
        int a;
        if (d < 128) a = OFF_XP0 + (i >> 1) * 256 + d * 2 + (i & 1);
        else { int o = d - 128, u = o / 3, m = o - 3 * u;
               a = OFF_XPV + ((i >> 1) * 3 + m) * XPV_STR + u * 2 + (i & 1); }
        sm[a] = v;
    }
    for (int e = tid; e < OFF_XP0; e += 320) sm[e] = 0.f;
    uint32_t smb = (uint32_t)__cvta_generic_to_shared(sm);
    __syncthreads();

    // ---- pipelined edge accumulation over this block's 8 receivers ----
    int gbeg = s_off[0], gend = s_off[8];
    for (int cpos = gbeg; cpos < gend; cpos += CHUNK) {
        int mm = gend - cpos; if (mm > CHUNK) mm = CHUNK;
        if (tid < mm) {
            int gp = cpos + tid;
            int eid = g_ord[gp];
            s_eid[tid] = eid;
            s_src[tid] = esrc[eid];
            int i = 0;
            #pragma unroll
            for (int q = 1; q < 8; q++) i += (gp >= s_off[q]);
            s_ri[tid] = i;
        }
        __syncthreads();
        int issued = 0;
        for (; issued < 2 && issued < mm; issued++) {
            stage_async(smb, issued & 3, cpos + issued, s_eid[issued], s_src[issued], eattr);
            CP_COMMIT();
        }
        for (int q = issued; q < 2; q++) CP_COMMIT();
        for (int k = 0; k < mm; k++) {
            if (issued < mm) {
                stage_async(smb, issued & 3, cpos + issued, s_eid[issued], s_src[issued], eattr);
                issued++;
            }
            CP_COMMIT();
            CP_WAIT2();
            __syncthreads();
            edge_accum(sm, k & 3, s_ri[k]);
        }
        __syncthreads();
    }

    // ---- scale r by attr/sqrt(10) ----
    for (int e = tid; e < 6144; e += 320) {
        int i, addr;
        if (e < 1536) {
            int p = e / 384, r = e - p * 384;
            i = 2 * p + (r & 1);
            addr = OFF_RP0 + p * 384 + r;
        } else {
            int e2 = e - 1536;
            int p = e2 / 1152, r2 = e2 - p * 1152;
            int m = r2 / 384, q = r2 - m * 384;
            i = 2 * p + (q & 1);
            addr = OFF_RPV + (p * 3 + m) * RPV_STR + q;
        }
        sm[addr] *= INV_SQRT10 * s_att[i];
    }
    __syncthreads();

    // ---- angle ----
    {
        int w = tid >> 5, l = tid & 31;
        if (w < 8) {
            float s = 0.f;
            for (int k = l; k < MID0; k += 32)
                s += sm[OFF_RP0 + (w >> 1) * 384 + 2 * k + (w & 1)] * l3w[k];
            #pragma unroll
            for (int o = 16; o; o >>= 1) s += __shfl_xor_sync(0xffffffffu, s, o);
            if (!l) s_ang[w] = 0.1f * INV_SQRT192 * s;
        }
    }
    __syncthreads();

    // ---- final GEMM: pair-packed fma.rn.f32x2 with float4 smem reads ----
    int j = tid;
    ull aS[4] = {0ull, 0ull, 0ull, 0ull}, aC[4] = {0ull, 0ull, 0ull, 0ull};
    float sS;
    if (j < MUL0) {
        #pragma unroll 2
        for (int k = 0; k < MUL0; k += 2) {
            ull wa = dupf(scw0[k * MUL0 + j]), wb = dupf(scw0[(k + 1) * MUL0 + j]);
            #pragma unroll
            for (int p = 0; p < 4; p++) {
                ulonglong2 x = *reinterpret_cast<const ulonglong2*>(&sm[OFF_XP0 + p * 256 + 2 * k]);
                fma2(aS[p], x.x, wa, aS[p]);
                fma2(aS[p], x.y, wb, aS[p]);
            }
        }
        #pragma unroll 2
        for (int c = 0; c < MID0; c += 2) {
            ull wa = dupf(l2w0[c * MUL0 + j]), wb = dupf(l2w0[(c + 1) * MUL0 + j]);
            #pragma unroll
            for (int p = 0; p < 4; p++) {
                ulonglong2 r = *reinterpret_cast<const ulonglong2*>(&sm[OFF_RP0 + p * 384 + 2 * c]);
                fma2(aC[p], r.x, wa, aC[p]);
                fma2(aC[p], r.y, wb, aC[p]);
            }
        }
        sS = INV_SQRT128;
    } else {
        int o = j - MUL0, v = o / 3, m = o - 3 * v;
        #pragma unroll 2
        for (int u = 0; u < MUL1; u += 2) {
            ull wa = dupf(scw1[u * MUL1 + v]), wb = dupf(scw1[(u + 1) * MUL1 + v]);
            #pragma unroll
            for (int p = 0; p < 4; p++) {
                ulonglong2 x = *reinterpret_cast<const ulonglong2*>(
                    &sm[OFF_XPV + (p * 3 + m) * XPV_STR + 2 * u]);
                fma2(aS[p], x.x, wa, aS[p]);
                fma2(aS[p], x.y, wb, aS[p]);
            }
        }
        #pragma unroll 2
        for (int c = 0; c < MID0; c += 2) {
            ull wa = dupf(l2w1[c * MUL1 + v]), wb = dupf(l2w1[(c + 1) * MUL1 + v]);
            #pragma unroll
            for (int p = 0; p < 4; p++) {
                ulonglong2 r = *reinterpret_cast<const ulonglong2*>(
                    &sm[OFF_RPV + (p * 3 + m) * RPV_STR + 2 * c]);
                fma2(aC[p], r.x, wa, aC[p]);
                fma2(aC[p], r.y, wb, aC[p]);
            }
        }
        sS = INV_SQRT64;
    }
    #pragma unroll
    for (int p = 0; p < 4; p++) {
        float2 S = unpack2(aS[p]), C = unpack2(aC[p]);
        int i0 = 2 * p;
        float a0 = s_ang[i0], a1 = s_ang[i0 + 1];
        out[(size_t)(p0 + i0) * DIM + j] =
            __cosf(a0) * S.x * sS + __sinf(a0) * C.x * INV_SQRT192;
        out[(size_t)(p0 + i0 + 1) * DIM + j] =
            __cosf(a1) * S.y * sS + __sinf(a1) * C.y * INV_SQRT192;
    }
}

// ---------------------------------------------------------------------------
// launch
// ---------------------------------------------------------------------------
extern "C" void kernel_launch(void* const* d_in, const int* in_sizes, int n_in,
                              void* d_out, int out_size) {
    const float* sender_input   = (const float*)d_in[0];
    const float* sender_attr    = (const float*)d_in[1];
    const float* receiver_input = (const float*)d_in[2];
    const float* receiver_attr  = (const float*)d_in[3];
    const int*   edge_src       = (const int*)d_in[4];
    const int*   edge_dst       = (const int*)d_in[5];
    const float* edge_attr      = (const float*)d_in[6];
    const float* edge_scalars   = (const float*)d_in[7];
    const float* fc_w1          = (const float*)d_in[8];
    const float* fc_w2          = (const float*)d_in[9];
    const float* lin1_w0        = (const float*)d_in[10];
    const float* lin1_w1        = (const float*)d_in[11];
    const float* sc_w0          = (const float*)d_in[12];
    const float* sc_w1          = (const float*)d_in[13];
    const float* lin2_w0        = (const float*)d_in[14];
    const float* lin2_w1        = (const float*)d_in[15];
    const float* lin3_w         = (const float*)d_in[16];
    float* out = (float*)d_out;

    zero_aux_kernel<<<(P_N + 255) / 256, 256>>>();
    sender_kernel<<<A_N, 192>>>(sender_input, sender_attr, lin1_w0, lin1_w1);
    hist_kernel<<<200, 1024>>>(edge_dst);
    scan_kernel<<<1, 1024>>>();
    scatter_kernel<<<200, 1024>>>(edge_dst);
    weight_kernel<<<E_N / 32, 384>>>(edge_scalars, fc_w1, fc_w2);
    fused_recv_kernel<<<P_N / 8, 320>>>(receiver_input, receiver_attr,
                                        edge_src, edge_attr,
                                        sc_w0, sc_w1, lin2_w0, lin2_w1, lin3_w,
                                        out);
}

// round 3
// speedup vs baseline: 1.2497x; 1.2497x over previous
#include <cuda_runtime.h>
#include <cstdint>
#include <cstddef>

// ---------------------------------------------------------------------------
// Problem constants
// ---------------------------------------------------------------------------
#define A_N   2000
#define P_N   20000
#define E_N   200000
#define MUL0  128
#define MUL1  64
#define DIM   320
#define MID0  192
#define RDIM  768

#define INV_SQRT10   0.31622776601683794f
#define INV_SQRT64   0.125f
#define INV_SQRT100  0.1f
#define INV_SQRT128  0.08838834764831845f
#define INV_SQRT192  0.07216878364870323f
#define INV_SQRT3    0.5773502691896258f

typedef unsigned long long ull;

// ---------------------------------------------------------------------------
// Device scratch
// ---------------------------------------------------------------------------
__device__ __align__(16) float g_s0[A_N * MUL0];
__device__ __align__(16) float g_s1[A_N * MID0];
__device__ __align__(16) float g_r[(size_t)P_N * RDIM];
__device__ int g_cnt[P_N];
__device__ int g_cur[P_N];
__device__ int g_off[P_N + 1];
__device__ int g_ssrc[E_N];    // sorted-order src
__device__ int g_sdst[E_N];    // sorted-order dst (non-decreasing)
__device__ int g_seid[E_N];    // sorted-order original edge id

// ---------------------------------------------------------------------------
// PTX helpers
// ---------------------------------------------------------------------------
__device__ __forceinline__ void fma2(ull& d, ull a, ull b, ull c) {
    asm("fma.rn.f32x2 %0, %1, %2, %3;" : "=l"(d) : "l"(a), "l"(b), "l"(c));
}
__device__ __forceinline__ float2 unpack2(ull v) {
    float2 r;
    asm("mov.b64 {%0, %1}, %2;" : "=f"(r.x), "=f"(r.y) : "l"(v));
    return r;
}
__device__ __forceinline__ ull dupf(float v) {
    ull r;
    asm("mov.b64 %0, {%1, %1};" : "=l"(r) : "f"(v));
    return r;
}
__device__ __forceinline__ void red4(float* p, float a, float b, float c, float d) {
    asm volatile("red.global.add.v4.f32 [%0], {%1, %2, %3, %4};"
                 :: "l"(p), "f"(a), "f"(b), "f"(c), "f"(d) : "memory");
}

// ---------------------------------------------------------------------------
// K0: zero accumulator + counters
// ---------------------------------------------------------------------------
__global__ void zero_r_kernel() {
    size_t n = (size_t)P_N * RDIM / 4;
    float4* p = reinterpret_cast<float4*>(g_r);
    float4 z = make_float4(0.f, 0.f, 0.f, 0.f);
    for (size_t i = (size_t)blockIdx.x * blockDim.x + threadIdx.x; i < n;
         i += (size_t)gridDim.x * blockDim.x)
        p[i] = z;
}
__global__ void zero_aux_kernel() {
    int i = blockIdx.x * blockDim.x + threadIdx.x;
    if (i < P_N) { g_cnt[i] = 0; g_cur[i] = 0; }
}

// ---------------------------------------------------------------------------
// K1: sender transform
// ---------------------------------------------------------------------------
__global__ __launch_bounds__(192) void sender_kernel(
    const float* __restrict__ sin_, const float* __restrict__ sattr,
    const float* __restrict__ w0,   const float* __restrict__ w1) {
    __shared__ float xs[DIM];
    int a = blockIdx.x, tid = threadIdx.x;
    float at = sattr[a];
    for (int idx = tid; idx < DIM; idx += 192)
        xs[idx] = sin_[(size_t)a * DIM + idx] * at;
    __syncthreads();
    if (tid < MUL0) {
        float acc = 0.f;
        #pragma unroll 8
        for (int u = 0; u < MUL0; u++) acc += xs[u] * w0[u * MUL0 + tid];
        g_s0[a * MUL0 + tid] = acc * INV_SQRT128;
    }
    {
        int o = tid, v = o / 3, m = o - v * 3;
        float acc = 0.f;
        #pragma unroll 8
        for (int u = 0; u < MUL1; u++) acc += xs[MUL0 + u * 3 + m] * w1[u * MUL1 + v];
        g_s1[a * MID0 + o] = acc * INV_SQRT64;
    }
}

// ---------------------------------------------------------------------------
// CSR sort by destination
// ---------------------------------------------------------------------------
__global__ void hist_kernel(const int* __restrict__ edst) {
    for (int e = blockIdx.x * blockDim.x + threadIdx.x; e < E_N;
         e += gridDim.x * blockDim.x)
        atomicAdd(&g_cnt[edst[e]], 1);
}

__global__ __launch_bounds__(1024) void scan_kernel() {
    __shared__ int wt[32];
    int t = threadIdx.x, lane = t & 31, w = t >> 5;
    int base = t * 20;
    int local[20];
    int s = 0;
    #pragma unroll
    for (int i = 0; i < 20; i++) {
        int c = (base + i < P_N) ? g_cnt[base + i] : 0;
        local[i] = s; s += c;
    }
    int v = s;
    #pragma unroll
    for (int off = 1; off < 32; off <<= 1) {
        int u = __shfl_up_sync(0xffffffffu, v, off);
        if (lane >= off) v += u;
    }
    if (lane == 31) wt[w] = v;
    __syncthreads();
    if (w == 0) {
        int x = wt[lane];
        #pragma unroll
        for (int off = 1; off < 32; off <<= 1) {
            int u = __shfl_up_sync(0xffffffffu, x, off);
            if (lane >= off) x += u;
        }
        wt[lane] = x;
    }
    __syncthreads();
    int pre = v - s + (w ? wt[w - 1] : 0);
    #pragma unroll
    for (int i = 0; i < 20; i++)
        if (base + i < P_N) g_off[base + i] = pre + local[i];
    if (t == 1023) g_off[P_N] = pre + s;
}

__global__ void scatter_kernel(const int* __restrict__ esrc,
                               const int* __restrict__ edst) {
    for (int e = blockIdx.x * blockDim.x + threadIdx.x; e < E_N;
         e += gridDim.x * blockDim.x) {
        int d = edst[e];
        int pos = g_off[d] + atomicAdd(&g_cur[d], 1);
        g_sdst[pos] = d;
        g_ssrc[pos] = esrc[e];
        g_seid[pos] = e;
    }
}

// ---------------------------------------------------------------------------
// K5: fused edge kernel on SORTED edges.
//   phase A: h = silu(escal@fc_w1/sqrt10)/sqrt100 -> smem dup pairs
//   phase B: weight quads via FFMA2 register GEMM
//   phase C: gather g0/g1, aggregate contributions over consecutive same-dst
//            edges in registers, red.v4 only on destination change.
// 384 threads: tx = tid%96 (weight quad), ty = tid/96; edges t = 8*ty + tt.
// ---------------------------------------------------------------------------
__global__ __launch_bounds__(384) void edge_kernel(
    const float* __restrict__ escal, const float* __restrict__ eattr,
    const float* __restrict__ fw1,   const float* __restrict__ fw2) {
    __shared__ float  s_scal[320];
    __shared__ float2 s_h[3200];
    __shared__ int    s_src[32], s_dst[32], s_eid[32];
    __shared__ float  s_att[128];

    int tid = threadIdx.x;
    int e0  = blockIdx.x * 32;

    if (tid < 32) {
        s_eid[tid] = g_seid[e0 + tid];
        s_src[tid] = g_ssrc[e0 + tid];
        s_dst[tid] = g_sdst[e0 + tid];
    }
    __syncthreads();
    if (tid < 320) {
        int t = tid / 10, b = tid - t * 10;
        s_scal[tid] = escal[(size_t)s_eid[t] * 10 + b];
    }
    if (tid < 128) {
        int t = tid >> 2, q = tid & 3;
        s_att[tid] = eattr[(size_t)s_eid[t] * 4 + q];
    }
    __syncthreads();

    // phase A
    for (int idx = tid; idx < 3200; idx += 384) {
        int t = idx / 100, k = idx - t * 100;
        float acc = 0.f;
        #pragma unroll
        for (int b = 0; b < 10; b++) acc += s_scal[t * 10 + b] * fw1[b * 100 + k];
        acc *= INV_SQRT10;
        float h = acc / (1.f + __expf(-acc)) * INV_SQRT100;
        s_h[t * 100 + k] = make_float2(h, h);
    }
    __syncthreads();

    int tx = tid % 96, ty = tid / 96;
    const ulonglong2* W2 = reinterpret_cast<const ulonglong2*>(fw2);
    const ull* H = reinterpret_cast<const ull*>(s_h);

    ull wacc[8][2];
    #pragma unroll
    for (int i = 0; i < 8; i++) { wacc[i][0] = 0ull; wacc[i][1] = 0ull; }

    // phase B: weight[8*ty+tt][4*tx .. 4*tx+3]
    #pragma unroll 4
    for (int k = 0; k < 100; k++) {
        ulonglong2 w = W2[k * 96 + tx];
        #pragma unroll
        for (int tt = 0; tt < 8; tt++) {
            ull hv = H[(8 * ty + tt) * 100 + k];    // uniform per warp -> broadcast
            fma2(wacc[tt][0], hv, w.x, wacc[tt][0]);
            fma2(wacc[tt][1], hv, w.y, wacc[tt][1]);
        }
    }

    // phase C: region by tx, run-aggregated scatter
    int t0 = 8 * ty;

    if (tx < 32) {
        // out0a[u] = w0*g0[u]*sh0 -> r[:, 4*tx .. ]
        float4 acc = make_float4(0.f, 0.f, 0.f, 0.f);
        int cur = s_dst[t0];
        #pragma unroll
        for (int tt = 0; tt < 8; tt++) {
            int t = t0 + tt, d = s_dst[t];
            if (d != cur) {
                red4(g_r + (size_t)cur * RDIM + 4 * tx, acc.x, acc.y, acc.z, acc.w);
                acc = make_float4(0.f, 0.f, 0.f, 0.f);
                cur = d;
            }
            float2 lo = unpack2(wacc[tt][0]), hi = unpack2(wacc[tt][1]);
            float sh0 = s_att[4 * t];
            const float4 g = *reinterpret_cast<const float4*>(&g_s0[s_src[t] * MUL0 + 4 * tx]);
            acc.x += lo.x * g.x * sh0;
            acc.y += lo.y * g.y * sh0;
            acc.z += hi.x * g.z * sh0;
            acc.w += hi.y * g.w * sh0;
        }
        red4(g_r + (size_t)cur * RDIM + 4 * tx, acc.x, acc.y, acc.z, acc.w);
    } else if (tx < 64) {
        // out1a[u][m] = w1*g0[u]*sh1[m] -> r[:, 192 + u*3 + m]
        int u0 = 4 * (tx - 32);
        float acc[12];
        #pragma unroll
        for (int i = 0; i < 12; i++) acc[i] = 0.f;
        int cur = s_dst[t0];
        #pragma unroll
        for (int tt = 0; tt < 8; tt++) {
            int t = t0 + tt, d = s_dst[t];
            if (d != cur) {
                float* b = g_r + (size_t)cur * RDIM + MID0 + 3 * u0;
                red4(b,     acc[0], acc[1], acc[2],  acc[3]);
                red4(b + 4, acc[4], acc[5], acc[6],  acc[7]);
                red4(b + 8, acc[8], acc[9], acc[10], acc[11]);
                #pragma unroll
                for (int i = 0; i < 12; i++) acc[i] = 0.f;
                cur = d;
            }
            float2 lo = unpack2(wacc[tt][0]), hi = unpack2(wacc[tt][1]);
            const float4 g = *reinterpret_cast<const float4*>(&g_s0[s_src[t] * MUL0 + u0]);
            float a0 = lo.x * g.x, a1 = lo.y * g.y, a2 = hi.x * g.z, a3 = hi.y * g.w;
            float sx = s_att[4 * t + 1], sy = s_att[4 * t + 2], sz = s_att[4 * t + 3];
            acc[0] += a0 * sx; acc[1]  += a0 * sy; acc[2]  += a0 * sz;
            acc[3] += a1 * sx; acc[4]  += a1 * sy; acc[5]  += a1 * sz;
            acc[6] += a2 * sx; acc[7]  += a2 * sy; acc[8]  += a2 * sz;
            acc[9] += a3 * sx; acc[10] += a3 * sy; acc[11] += a3 * sz;
        }
        float* b = g_r + (size_t)cur * RDIM + MID0 + 3 * u0;
        red4(b,     acc[0], acc[1], acc[2],  acc[3]);
        red4(b + 4, acc[4], acc[5], acc[6],  acc[7]);
        red4(b + 8, acc[8], acc[9], acc[10], acc[11]);
    } else if (tx < 80) {
        // out1b[v][m] = w2*g1[v][m]*sh0 -> r[:, 576 + v*3 + m]
        int v0 = 4 * (tx - 64);
        float acc[12];
        #pragma unroll
        for (int i = 0; i < 12; i++) acc[i] = 0.f;
        int cur = s_dst[t0];
        #pragma unroll
        for (int tt = 0; tt < 8; tt++) {
            int t = t0 + tt, d = s_dst[t];
            if (d != cur) {
                float* b = g_r + (size_t)cur * RDIM + 576 + 3 * v0;
                red4(b,     acc[0], acc[1], acc[2],  acc[3]);
                red4(b + 4, acc[4], acc[5], acc[6],  acc[7]);
                red4(b + 8, acc[8], acc[9], acc[10], acc[11]);
                #pragma unroll
                for (int i = 0; i < 12; i++) acc[i] = 0.f;
                cur = d;
            }
            float2 lo = unpack2(wacc[tt][0]), hi = unpack2(wacc[tt][1]);
            float sh0 = s_att[4 * t];
            float q0 = lo.x * sh0, q1 = lo.y * sh0, q2 = hi.x * sh0, q3 = hi.y * sh0;
            const float4* gp = reinterpret_cast<const float4*>(&g_s1[s_src[t] * MID0 + 3 * v0]);
            float4 gA = gp[0], gB = gp[1], gC = gp[2];
            acc[0] += q0 * gA.x; acc[1]  += q0 * gA.y; acc[2]  += q0 * gA.z;
            acc[3] += q1 * gA.w; acc[4]  += q1 * gB.x; acc[5]  += q1 * gB.y;
            acc[6] += q2 * gB.z; acc[7]  += q2 * gB.w; acc[8]  += q2 * gC.x;
            acc[9] += q3 * gC.y; acc[10] += q3 * gC.z; acc[11] += q3 * gC.w;
        }
        float* b = g_r + (size_t)cur * RDIM + 576 + 3 * v0;
        red4(b,     acc[0], acc[1], acc[2],  acc[3]);
        red4(b + 4, acc[4], acc[5], acc[6],  acc[7]);
        red4(b + 8, acc[8], acc[9], acc[10], acc[11]);
    } else {
        // out0b[v] = w3*dot(g1[v],sh1)/sqrt3 -> r[:, 128 + v]
        int v0 = 4 * (tx - 80);
        float4 acc = make_float4(0.f, 0.f, 0.f, 0.f);
        int cur = s_dst[t0];
        #pragma unroll
        for (int tt = 0; tt < 8; tt++) {
            int t = t0 + tt, d = s_dst[t];
            if (d != cur) {
                red4(g_r + (size_t)cur * RDIM + MUL0 + v0, acc.x, acc.y, acc.z, acc.w);
                acc = make_float4(0.f, 0.f, 0.f, 0.f);
                cur = d;
            }
            float2 lo = unpack2(wacc[tt][0]), hi = unpack2(wacc[tt][1]);
            float sx = s_att[4 * t + 1], sy = s_att[4 * t + 2], sz = s_att[4 * t + 3];
            const float4* gp = reinterpret_cast<const float4*>(&g_s1[s_src[t] * MID0 + 3 * v0]);
            float4 gA = gp[0], gB = gp[1], gC = gp[2];
            float d0 = gA.x * sx + gA.y * sy + gA.z * sz;
            float d1 = gA.w * sx + gB.x * sy + gB.y * sz;
            float d2 = gB.z * sx + gB.w * sy + gC.x * sz;
            float d3 = gC.y * sx + gC.z * sy + gC.w * sz;
            acc.x += lo.x * d0 * INV_SQRT3;
            acc.y += lo.y * d1 * INV_SQRT3;
            acc.z += hi.x * d2 * INV_SQRT3;
            acc.w += hi.y * d3 * INV_SQRT3;
        }
        red4(g_r + (size_t)cur * RDIM + MUL0 + v0, acc.x, acc.y, acc.z, acc.w);
    }
}

// ---------------------------------------------------------------------------
// K6: receiver kernel.  Load g_r -> packed smem, pair-packed FFMA2 GEMM.
// 8 receivers/block, 320 threads.
// ---------------------------------------------------------------------------
#define OFF_RP0 0
#define OFF_RPV 1536
#define RPV_STR 388
#define OFF_XP0 6192
#define OFF_XPV 7216
#define XPV_STR 132
#define SMF     8800

__global__ __launch_bounds__(320, 3) void recv_kernel(
    const float* __restrict__ rin,  const float* __restrict__ rattr,
    const float* __restrict__ scw0, const float* __restrict__ scw1,
    const float* __restrict__ l2w0, const float* __restrict__ l2w1,
    const float* __restrict__ l3w,  float* __restrict__ out) {
    __shared__ __align__(16) float sm[SMF];
    __shared__ float s_att[8], s_ang[8];

    int tid = threadIdx.x;
    int p0  = blockIdx.x * 8;

    if (tid < 8) s_att[tid] = rattr[p0 + tid];
    __syncthreads();

    // load r into packed pair layout (scaled by attr/sqrt(10))
    for (int idx = tid; idx < 8 * RDIM; idx += 320) {
        int i = idx / RDIM, c = idx - i * RDIM;
        float v = g_r[(size_t)(p0 + i) * RDIM + c] * (INV_SQRT10 * s_att[i]);
        int addr;
        if (c < 192) {
            addr = OFF_RP0 + (i >> 1) * 384 + 2 * c + (i & 1);
        } else if (c < 576) {
            int o = c - 192, u = o / 3, m = o - 3 * u;
            addr = OFF_RPV + ((i >> 1) * 3 + m) * RPV_STR + 2 * u + (i & 1);
        } else {
            int o = c - 576, v2 = o / 3, m = o - 3 * v2;
            addr = OFF_RPV + ((i >> 1) * 3 + m) * RPV_STR + 2 * (128 + v2) + (i & 1);
        }
        sm[addr] = v;
    }
    // load x into packed layout (with attr)
    for (int idx = tid; idx < 8 * DIM; idx += 320) {
        int i = idx / DIM, d = idx - i * DIM;
        float v = rin[(size_t)(p0 + i) * DIM + d] * s_att[i];
        int a;
        if (d < 128) a = OFF_XP0 + (i >> 1) * 256 + 2 * d + (i & 1);
        else { int o = d - 128, u = o / 3, m = o - 3 * u;
               a = OFF_XPV + ((i >> 1) * 3 + m) * XPV_STR + 2 * u + (i & 1); }
        sm[a] = v;
    }
    __syncthreads();

    // angle
    {
        int w = tid >> 5, l = tid & 31;
        if (w < 8) {
            float s = 0.f;
            for (int k = l; k < MID0; k += 32)
                s += sm[OFF_RP0 + (w >> 1) * 384 + 2 * k + (w & 1)] * l3w[k];
            #pragma unroll
            for (int o = 16; o; o >>= 1) s += __shfl_xor_sync(0xffffffffu, s, o);
            if (!l) s_ang[w] = 0.1f * INV_SQRT192 * s;
        }
    }
    __syncthreads();

    // final GEMM
    int j = tid;
    ull aS[4] = {0ull, 0ull, 0ull, 0ull}, aC[4] = {0ull, 0ull, 0ull, 0ull};
    float sS;
    if (j < MUL0) {
        #pragma unroll 2
        for (int k = 0; k < MUL0; k += 2) {
            ull wa = dupf(scw0[k * MUL0 + j]), wb = dupf(scw0[(k + 1) * MUL0 + j]);
            #pragma unroll
            for (int p = 0; p < 4; p++) {
                ulonglong2 x = *reinterpret_cast<const ulonglong2*>(&sm[OFF_XP0 + p * 256 + 2 * k]);
                fma2(aS[p], x.x, wa, aS[p]);
                fma2(aS[p], x.y, wb, aS[p]);
            }
        }
        #pragma unroll 2
        for (int c = 0; c < MID0; c += 2) {
            ull wa = dupf(l2w0[c * MUL0 + j]), wb = dupf(l2w0[(c + 1) * MUL0 + j]);
            #pragma unroll
            for (int p = 0; p < 4; p++) {
                ulonglong2 r = *reinterpret_cast<const ulonglong2*>(&sm[OFF_RP0 + p * 384 + 2 * c]);
                fma2(aC[p], r.x, wa, aC[p]);
                fma2(aC[p], r.y, wb, aC[p]);
            }
        }
        sS = INV_SQRT128;
    } else {
        int o = j - MUL0, v = o / 3, m = o - 3 * v;
        #pragma unroll 2
        for (int u = 0; u < MUL1; u += 2) {
            ull wa = dupf(scw1[u * MUL1 + v]), wb = dupf(scw1[(u + 1) * MUL1 + v]);
            #pragma unroll
            for (int p = 0; p < 4; p++) {
                ulonglong2 x = *reinterpret_cast<const ulonglong2*>(
                    &sm[OFF_XPV + (p * 3 + m) * XPV_STR + 2 * u]);
                fma2(aS[p], x.x, wa, aS[p]);
                fma2(aS[p], x.y, wb, aS[p]);
            }
        }
        #pragma unroll 2
        for (int c = 0; c < MID0; c += 2) {
            ull wa = dupf(l2w1[c * MUL1 + v]), wb = dupf(l2w1[(c + 1) * MUL1 + v]);
            #pragma unroll
            for (int p = 0; p < 4; p++) {
                ulonglong2 r = *reinterpret_cast<const ulonglong2*>(
                    &sm[OFF_RPV + (p * 3 + m) * RPV_STR + 2 * c]);
                fma2(aC[p], r.x, wa, aC[p]);
                fma2(aC[p], r.y, wb, aC[p]);
            }
        }
        sS = INV_SQRT64;
    }
    #pragma unroll
    for (int p = 0; p < 4; p++) {
        float2 S = unpack2(aS[p]), C = unpack2(aC[p]);
        int i0 = 2 * p;
        float a0 = s_ang[i0], a1 = s_ang[i0 + 1];
        out[(size_t)(p0 + i0) * DIM + j] =
            __cosf(a0) * S.x * sS + __sinf(a0) * C.x * INV_SQRT192;
        out[(size_t)(p0 + i0 + 1) * DIM + j] =
            __cosf(a1) * S.y * sS + __sinf(a1) * C.y * INV_SQRT192;
    }
}

// ---------------------------------------------------------------------------
// launch
// ---------------------------------------------------------------------------
extern "C" void kernel_launch(void* const* d_in, const int* in_sizes, int n_in,
                              void* d_out, int out_size) {
    const float* sender_input   = (const float*)d_in[0];
    const float* sender_attr    = (const float*)d_in[1];
    const float* receiver_input = (const float*)d_in[2];
    const float* receiver_attr  = (const float*)d_in[3];
    const int*   edge_src       = (const int*)d_in[4];
    const int*   edge_dst       = (const int*)d_in[5];
    const float* edge_attr      = (const float*)d_in[6];
    const float* edge_scalars   = (const float*)d_in[7];
    const float* fc_w1          = (const float*)d_in[8];
    const float* fc_w2          = (const float*)d_in[9];
    const float* lin1_w0        = (const float*)d_in[10];
    const float* lin1_w1        = (const float*)d_in[11];
    const float* sc_w0          = (const float*)d_in[12];
    const float* sc_w1          = (const float*)d_in[13];
    const float* lin2_w0        = (const float*)d_in[14];
    const float* lin2_w1        = (const float*)d_in[15];
    const float* lin3_w         = (const float*)d_in[16];
    float* out = (float*)d_out;

    zero_r_kernel<<<2048, 256>>>();
    zero_aux_kernel<<<(P_N + 255) / 256, 256>>>();
    sender_kernel<<<A_N, 192>>>(sender_input, sender_attr, lin1_w0, lin1_w1);
    hist_kernel<<<200, 1024>>>(edge_dst);
    scan_kernel<<<1, 1024>>>();
    scatter_kernel<<<200, 1024>>>(edge_src, edge_dst);
    edge_kernel<<<E_N / 32, 384>>>(edge_scalars, edge_attr, fc_w1, fc_w2);
    recv_kernel<<<P_N / 8, 320>>>(receiver_input, receiver_attr, sc_w0, sc_w1,
                                  lin2_w0, lin2_w1, lin3_w, out);
}